// round 2
// baseline (speedup 1.0000x reference)
#include <cuda_runtime.h>
#include <cuda_bf16.h>
#include <math.h>

// Problem constants
#define BB 2048
#define TT 256
#define FF 64
#define HH 32
#define G3 96   // 3*H

// Scratch for input-gate projections xg[t][b][96]  (201 MB, static device alloc)
__device__ float g_xg[(size_t)TT * BB * G3];

// ---------------------------------------------------------------------------
// Kernel 1: xg[(t*B + b)*96 + g] = sum_k x[b,t,k] * W_ih[g,k] + b_ih[g]
// Tile: 64 b-rows x 96 gate-cols at a fixed t. 192 threads, each 4 rows x 8 cols.
// Row padding chosen so all LDS.128 are 16B-aligned (68 & 100 are mult of 4).
// ---------------------------------------------------------------------------
__global__ __launch_bounds__(192) void xg_gemm_kernel(
    const float* __restrict__ x,      // [B, T, F]
    const float* __restrict__ W_ih,   // [96, 64]
    const float* __restrict__ b_ih)   // [96]
{
    __shared__ float As[64][68];   // [k][row]  (pad mult-of-4 -> aligned LDS.128)
    __shared__ float Ws[64][100];  // [k][g]

    const int t  = blockIdx.y;          // 0..255
    const int b0 = blockIdx.x * 64;     // 0..2047 step 64
    const int tid = threadIdx.x;        // 0..191
    const int rg = tid & 15;            // row group: rows rg*4 .. rg*4+3
    const int cg = tid >> 4;            // col group: cols cg*8 .. cg*8+7

    // Stage x tile: As[k][row] = x[(b0+row)*T*F + t*F + k]
    for (int idx = tid; idx < 64 * 64; idx += 192) {
        int row = idx >> 6;
        int k   = idx & 63;
        As[k][row] = x[((size_t)(b0 + row) * TT + t) * FF + k];
    }
    // Stage W: Ws[k][g] = W_ih[g*64 + k]
    for (int idx = tid; idx < G3 * FF; idx += 192) {
        int g = idx >> 6;
        int k = idx & 63;
        Ws[k][g] = W_ih[idx];
    }
    __syncthreads();

    float acc[4][8];
#pragma unroll
    for (int u = 0; u < 4; u++)
#pragma unroll
        for (int v = 0; v < 8; v++)
            acc[u][v] = b_ih[cg * 8 + v];

#pragma unroll
    for (int k = 0; k < 64; k++) {
        float4 a  = *reinterpret_cast<const float4*>(&As[k][rg * 4]);
        float4 w0 = *reinterpret_cast<const float4*>(&Ws[k][cg * 8]);
        float4 w1 = *reinterpret_cast<const float4*>(&Ws[k][cg * 8 + 4]);
        float av[4] = {a.x, a.y, a.z, a.w};
        float wv[8] = {w0.x, w0.y, w0.z, w0.w, w1.x, w1.y, w1.z, w1.w};
#pragma unroll
        for (int u = 0; u < 4; u++)
#pragma unroll
            for (int v = 0; v < 8; v++)
                acc[u][v] = fmaf(av[u], wv[v], acc[u][v]);
    }

    // Write xg: row (t*B + b0 + rg*4+u), cols cg*8..cg*8+7 (two float4 stores)
#pragma unroll
    for (int u = 0; u < 4; u++) {
        size_t base = ((size_t)t * BB + (b0 + rg * 4 + u)) * G3 + cg * 8;
        float4 o0 = make_float4(acc[u][0], acc[u][1], acc[u][2], acc[u][3]);
        float4 o1 = make_float4(acc[u][4], acc[u][5], acc[u][6], acc[u][7]);
        *reinterpret_cast<float4*>(&g_xg[base])     = o0;
        *reinterpret_cast<float4*>(&g_xg[base + 4]) = o1;
    }
}

// ---------------------------------------------------------------------------
// Kernel 2: recurrent GRU. One warp per batch element; lane i owns hidden
// unit i. W_hh rows {i, 32+i, 64+i} live in registers (96 regs/lane).
// h broadcast via shfl. Fused sigmoid head at the end.
// ---------------------------------------------------------------------------
__global__ __launch_bounds__(128) void gru_recurrent_kernel(
    const float* __restrict__ W_hh,    // [96, 32]
    const float* __restrict__ b_hh,    // [96]
    const float* __restrict__ W_head,  // [32]
    const float* __restrict__ b_head,  // [1]
    float* __restrict__ out)           // [B]
{
    const int warp = (blockIdx.x * blockDim.x + threadIdx.x) >> 5;
    const int lane = threadIdx.x & 31;
    if (warp >= BB) return;
    const int b = warp;

    float wr[HH], wz[HH], wn[HH];
#pragma unroll
    for (int j = 0; j < HH; j++) {
        wr[j] = W_hh[(0 * HH + lane) * HH + j];
        wz[j] = W_hh[(1 * HH + lane) * HH + j];
        wn[j] = W_hh[(2 * HH + lane) * HH + j];
    }
    const float bhr = b_hh[lane];
    const float bhz = b_hh[HH + lane];
    const float bhn = b_hh[2 * HH + lane];

    float h = 0.0f;
    const float* xgp = g_xg + (size_t)b * G3;

    for (int t = 0; t < TT; t++, xgp += (size_t)BB * G3) {
        float hr = bhr, hz = bhz, hn = bhn;
#pragma unroll
        for (int j = 0; j < HH; j++) {
            float hj = __shfl_sync(0xffffffffu, h, j);
            hr = fmaf(wr[j], hj, hr);
            hz = fmaf(wz[j], hj, hz);
            hn = fmaf(wn[j], hj, hn);
        }
        float xr = xgp[lane];
        float xz = xgp[HH + lane];
        float xn = xgp[2 * HH + lane];
        float r = 1.0f / (1.0f + __expf(-(xr + hr)));
        float z = 1.0f / (1.0f + __expf(-(xz + hz)));
        float n = tanhf(xn + r * hn);
        h = (1.0f - z) * n + z * h;
    }

    // Head: y = sigmoid(h . W_head + b_head)
    float v = h * W_head[lane];
#pragma unroll
    for (int off = 16; off > 0; off >>= 1)
        v += __shfl_xor_sync(0xffffffffu, v, off);
    if (lane == 0)
        out[b] = 1.0f / (1.0f + __expf(-(v + b_head[0])));
}

// ---------------------------------------------------------------------------
extern "C" void kernel_launch(void* const* d_in, const int* in_sizes, int n_in,
                              void* d_out, int out_size)
{
    const float* x      = (const float*)d_in[0];  // [B,T,F]
    const float* W_ih   = (const float*)d_in[1];  // [96,64]
    const float* W_hh   = (const float*)d_in[2];  // [96,32]
    const float* b_ih   = (const float*)d_in[3];  // [96]
    const float* b_hh   = (const float*)d_in[4];  // [96]
    const float* W_head = (const float*)d_in[5];  // [1,32]
    const float* b_head = (const float*)d_in[6];  // [1]
    float* out = (float*)d_out;                   // [B,1] = 2048 floats

    dim3 g1(BB / 64, TT);
    xg_gemm_kernel<<<g1, 192>>>(x, W_ih, b_ih);

    gru_recurrent_kernel<<<(BB * 32) / 128, 128>>>(W_hh, b_hh, W_head, b_head, out);
}

// round 4
// speedup vs baseline: 1.0675x; 1.0675x over previous
#include <cuda_runtime.h>
#include <cuda_bf16.h>
#include <math.h>

// Problem constants
#define BB 2048
#define TT 256
#define FF 64
#define HH 32
#define G3 96   // 3*H

typedef unsigned long long ull;

// Scratch for input-gate projections xg[t][b][96]  (201 MB, static device alloc)
__device__ float g_xg[(size_t)TT * BB * G3];

// ---- f32x2 packed helpers (sm_100+ PTX) -----------------------------------
__device__ __forceinline__ ull ffma2(ull a, ull b, ull c) {
    ull d;
    asm("fma.rn.f32x2 %0, %1, %2, %3;" : "=l"(d) : "l"(a), "l"(b), "l"(c));
    return d;
}
__device__ __forceinline__ ull pack2(float lo, float hi) {
    ull d;
    asm("mov.b64 %0, {%1, %2};" : "=l"(d) : "f"(lo), "f"(hi));
    return d;
}

// ---------------------------------------------------------------------------
// Kernel 1: xg[(t*B + b)*96 + g] = sum_k x[b,t,k] * W_ih[g,k] + b_ih[g]
// Tile: 64 b-rows x 96 gate-cols at fixed t. 192 threads, each 4 rows x 8 cols.
// Inner product done with fma.rn.f32x2 (column pairs) -> 2x fp32 rate.
// ---------------------------------------------------------------------------
__global__ __launch_bounds__(192) void xg_gemm_kernel(
    const float* __restrict__ x,      // [B, T, F]
    const float* __restrict__ W_ih,   // [96, 64]
    const float* __restrict__ b_ih)   // [96]
{
    __shared__ float As[64][68];   // [k][row]  row stride 272B (16B-mult)
    __shared__ float Ws[64][100];  // [k][g]    row stride 400B (16B-mult)

    const int t  = blockIdx.y;
    const int b0 = blockIdx.x * 64;
    const int tid = threadIdx.x;        // 0..191
    const int rg = tid & 15;            // rows rg*4 .. rg*4+3
    const int cg = tid >> 4;            // cols cg*8 .. cg*8+7

    for (int idx = tid; idx < 64 * 64; idx += 192) {
        int row = idx >> 6;
        int k   = idx & 63;
        As[k][row] = x[((size_t)(b0 + row) * TT + t) * FF + k];
    }
    for (int idx = tid; idx < G3 * FF; idx += 192) {
        int g = idx >> 6;
        int k = idx & 63;
        Ws[k][g] = W_ih[idx];
    }
    __syncthreads();

    // acc2[u][v]: packed pair = cols (cg*8+2v, cg*8+2v+1) for row rg*4+u
    ull acc2[4][4];
#pragma unroll
    for (int v = 0; v < 4; v++) {
        ull bias = pack2(b_ih[cg * 8 + 2 * v], b_ih[cg * 8 + 2 * v + 1]);
#pragma unroll
        for (int u = 0; u < 4; u++)
            acc2[u][v] = bias;
    }

#pragma unroll
    for (int k = 0; k < 64; k++) {
        float4 a = *reinterpret_cast<const float4*>(&As[k][rg * 4]);
        ulonglong2 wa = *reinterpret_cast<const ulonglong2*>(&Ws[k][cg * 8]);
        ulonglong2 wb = *reinterpret_cast<const ulonglong2*>(&Ws[k][cg * 8 + 4]);
        ull wv[4] = {wa.x, wa.y, wb.x, wb.y};
        ull ad[4] = {pack2(a.x, a.x), pack2(a.y, a.y),
                     pack2(a.z, a.z), pack2(a.w, a.w)};
#pragma unroll
        for (int u = 0; u < 4; u++)
#pragma unroll
            for (int v = 0; v < 4; v++)
                acc2[u][v] = ffma2(ad[u], wv[v], acc2[u][v]);
    }

    // Store: pairs are bit-identical to consecutive floats. base is 32B-aligned.
#pragma unroll
    for (int u = 0; u < 4; u++) {
        size_t base = ((size_t)t * BB + (b0 + rg * 4 + u)) * G3 + cg * 8;
        ulonglong2 s0 = make_ulonglong2(acc2[u][0], acc2[u][1]);
        ulonglong2 s1 = make_ulonglong2(acc2[u][2], acc2[u][3]);
        *reinterpret_cast<ulonglong2*>(&g_xg[base])     = s0;
        *reinterpret_cast<ulonglong2*>(&g_xg[base + 4]) = s1;
    }
}

// ---------------------------------------------------------------------------
// Kernel 2: recurrent GRU. One warp per batch element; lane i owns hidden
// unit i. W_hh rows {i, 32+i, 64+i} in registers. h broadcast via shfl.
// Software-prefetch next timestep's xg; split FMA chains even/odd.
// ---------------------------------------------------------------------------
__global__ __launch_bounds__(128) void gru_recurrent_kernel(
    const float* __restrict__ W_hh,    // [96, 32]
    const float* __restrict__ b_hh,    // [96]
    const float* __restrict__ W_head,  // [32]
    const float* __restrict__ b_head,  // [1]
    float* __restrict__ out)           // [B]
{
    const int warp = (blockIdx.x * blockDim.x + threadIdx.x) >> 5;
    const int lane = threadIdx.x & 31;
    if (warp >= BB) return;
    const int b = warp;

    float wr[HH], wz[HH], wn[HH];
#pragma unroll
    for (int j = 0; j < HH; j++) {
        wr[j] = W_hh[(0 * HH + lane) * HH + j];
        wz[j] = W_hh[(1 * HH + lane) * HH + j];
        wn[j] = W_hh[(2 * HH + lane) * HH + j];
    }
    const float bhr = b_hh[lane];
    const float bhz = b_hh[HH + lane];
    const float bhn = b_hh[2 * HH + lane];

    float h = 0.0f;
    const float* xgp = g_xg + (size_t)b * G3;

    // Prefetch t=0
    float pxr = xgp[lane];
    float pxz = xgp[HH + lane];
    float pxn = xgp[2 * HH + lane];

    for (int t = 0; t < TT; t++) {
        float xr = pxr, xz = pxz, xn = pxn;

        // Issue next step's loads NOW (h-independent) to hide DRAM latency.
        xgp += (size_t)BB * G3;
        const float* pf = (t + 1 < TT) ? xgp : (xgp - (size_t)BB * G3);
        pxr = pf[lane];
        pxz = pf[HH + lane];
        pxn = pf[2 * HH + lane];

        // h @ W_hh^T with split (even/odd) accumulation chains
        float hr0 = bhr, hz0 = bhz, hn0 = bhn;
        float hr1 = 0.0f, hz1 = 0.0f, hn1 = 0.0f;
#pragma unroll
        for (int j = 0; j < HH; j += 2) {
            float hj0 = __shfl_sync(0xffffffffu, h, j);
            float hj1 = __shfl_sync(0xffffffffu, h, j + 1);
            hr0 = fmaf(wr[j], hj0, hr0);
            hz0 = fmaf(wz[j], hj0, hz0);
            hn0 = fmaf(wn[j], hj0, hn0);
            hr1 = fmaf(wr[j + 1], hj1, hr1);
            hz1 = fmaf(wz[j + 1], hj1, hz1);
            hn1 = fmaf(wn[j + 1], hj1, hn1);
        }
        float hr = hr0 + hr1;
        float hz = hz0 + hz1;
        float hn = hn0 + hn1;

        float r = 1.0f / (1.0f + __expf(-(xr + hr)));
        float z = 1.0f / (1.0f + __expf(-(xz + hz)));
        float n = tanhf(xn + r * hn);
        h = (1.0f - z) * n + z * h;
    }

    // Head: y = sigmoid(h . W_head + b_head)
    float v = h * W_head[lane];
#pragma unroll
    for (int off = 16; off > 0; off >>= 1)
        v += __shfl_xor_sync(0xffffffffu, v, off);
    if (lane == 0)
        out[b] = 1.0f / (1.0f + __expf(-(v + b_head[0])));
}

// ---------------------------------------------------------------------------
extern "C" void kernel_launch(void* const* d_in, const int* in_sizes, int n_in,
                              void* d_out, int out_size)
{
    const float* x      = (const float*)d_in[0];  // [B,T,F]
    const float* W_ih   = (const float*)d_in[1];  // [96,64]
    const float* W_hh   = (const float*)d_in[2];  // [96,32]
    const float* b_ih   = (const float*)d_in[3];  // [96]
    const float* b_hh   = (const float*)d_in[4];  // [96]
    const float* W_head = (const float*)d_in[5];  // [1,32]
    const float* b_head = (const float*)d_in[6];  // [1]
    float* out = (float*)d_out;                   // [B,1] = 2048 floats

    dim3 g1(BB / 64, TT);
    xg_gemm_kernel<<<g1, 192>>>(x, W_ih, b_ih);

    gru_recurrent_kernel<<<(BB * 32) / 128, 128>>>(W_hh, b_hh, W_head, b_head, out);
}